// round 14
// baseline (speedup 1.0000x reference)
#include <cuda_runtime.h>
#include <cuda_fp16.h>
#include <cstdint>

#define TOTAL    8192
#define HIDDEN   1280
#define HEADS    16
#define HEAD_DIM 80
#define NCHUNK   8
#define CHUNK_L  1024
#define QKVN     3840
#define SCALE    0.11180339887498949f  /* 80^-0.5 */

// ---------------- device scratch (no allocs allowed) ----------------
__device__ __half g_QK16[(size_t)TOTAL * 2 * HIDDEN];      // fp16 q|k (GEMM epi)
__device__ __half g_V16 [(size_t)TOTAL * HIDDEN];          // fp16 v  (GEMM epi)
__device__ __half g_Aq  [(size_t)TOTAL * HIDDEN];          // fp16(x)
__device__ __half g_Ap  [(size_t)TOTAL * HIDDEN];          // fp16(attn)
__device__ __half g_Bq  [(size_t)QKVN  * HIDDEN];          // fp16(w_qkv)^T
__device__ __half g_Bp  [(size_t)HIDDEN* HIDDEN];          // fp16(w_proj)^T
__device__ __half g_Q1 [(size_t)TOTAL * HEADS * HEAD_DIM]; // fp16 roped q
__device__ __half g_K1 [(size_t)TOTAL * HEADS * HEAD_DIM]; // fp16 roped k

// ---------------- PTX helpers ----------------
__device__ __forceinline__ uint32_t smem_u32(const void* p) {
    uint32_t a;
    asm("{ .reg .u64 t; cvta.to.shared.u64 t, %1; cvt.u32.u64 %0, t; }"
        : "=r"(a) : "l"(p));
    return a;
}
__device__ __forceinline__ void ldsm_x4(uint32_t* r, uint32_t addr) {
    asm volatile("ldmatrix.sync.aligned.m8n8.x4.shared.b16 {%0,%1,%2,%3}, [%4];"
                 : "=r"(r[0]), "=r"(r[1]), "=r"(r[2]), "=r"(r[3]) : "r"(addr));
}
__device__ __forceinline__ void ldsm_x4_t(uint32_t* r, uint32_t addr) {
    asm volatile("ldmatrix.sync.aligned.m8n8.x4.trans.shared.b16 {%0,%1,%2,%3}, [%4];"
                 : "=r"(r[0]), "=r"(r[1]), "=r"(r[2]), "=r"(r[3]) : "r"(addr));
}
__device__ __forceinline__ void mma_16816(float* c, const uint32_t* a,
                                          const uint32_t* b) {
    asm volatile(
        "mma.sync.aligned.m16n8k16.row.col.f32.f16.f16.f32 "
        "{%0,%1,%2,%3}, {%4,%5,%6,%7}, {%8,%9}, {%0,%1,%2,%3};"
        : "+f"(c[0]), "+f"(c[1]), "+f"(c[2]), "+f"(c[3])
        : "r"(a[0]), "r"(a[1]), "r"(a[2]), "r"(a[3]), "r"(b[0]), "r"(b[1]));
}
__device__ __forceinline__ void cp16(uint32_t dst, const void* src) {
    asm volatile("cp.async.cg.shared.global [%0], [%1], 16;"
                 :: "r"(dst), "l"(src));
}
__device__ __forceinline__ void cp_commit() {
    asm volatile("cp.async.commit_group;" ::: "memory");
}
template <int W>
__device__ __forceinline__ void cp_wait() {
    asm volatile("cp.async.wait_group %0;" :: "n"(W) : "memory");
}
__device__ __forceinline__ uint32_t pack2h(__half lo, __half hi) {
    return (uint32_t)__half_as_ushort(lo) |
           ((uint32_t)__half_as_ushort(hi) << 16);
}
union U2H4 { uint2 u; __half h[4]; };

// ---------------------------------------------------------------------------
// Tensor-core GEMM: out = A * B^T + bias. QKV mode (QK16 != null): fp16 out,
// cols < 2*HIDDEN to QK16, rest to V16. Proj mode: fp32 to C.
// ---------------------------------------------------------------------------
#define BK     32
#define NST    3
#define LDAE   40
#define ROWB   (LDAE * 2)
#define STAGEB (128 * ROWB)
#define BOFF   (NST * STAGEB)
#define GSMEM  (2 * NST * STAGEB)

__global__ __launch_bounds__(128, 2) void gemm_fp16_mma(
    const __half* __restrict__ A, const __half* __restrict__ B,
    const float* __restrict__ bias, float* __restrict__ C,
    __half* __restrict__ QK16, __half* __restrict__ V16, int N, int K)
{
    extern __shared__ char sm[];
    const int tid  = threadIdx.x;
    const int wid  = tid >> 5;
    const int lane = tid & 31;
    const int m0   = blockIdx.y * 128;
    const int n0   = blockIdx.x * 128;
    const int wm   = wid & 1;
    const int wn   = wid >> 1;

    uint32_t aDst[4], bDst[4];
    const __half *aS[4], *bS[4];
#pragma unroll
    for (int p = 0; p < 4; p++) {
        int u  = tid + p * 128;
        int r  = u >> 2;
        int ch = (u & 3) * 8;
        aDst[p] = smem_u32(sm + r * ROWB + ch * 2);
        bDst[p] = aDst[p] + BOFF;
        aS[p]   = A + (size_t)(m0 + r) * K + ch;
        bS[p]   = B + (size_t)(n0 + r) * K + ch;
    }

    float acc[4][8][4];
#pragma unroll
    for (int mt = 0; mt < 4; mt++)
#pragma unroll
        for (int nt = 0; nt < 8; nt++)
#pragma unroll
            for (int v = 0; v < 4; v++) acc[mt][nt][v] = 0.0f;

    const int lrow  = lane & 15;
    const int lcolb = ((lane >> 4) << 3) * 2;
    uint32_t aAddr[4], bAddr[4];
#pragma unroll
    for (int mt = 0; mt < 4; mt++)
        aAddr[mt] = smem_u32(sm + (wm * 64 + mt * 16 + lrow) * ROWB + lcolb);
#pragma unroll
    for (int np = 0; np < 4; np++)
        bAddr[np] = smem_u32(sm + BOFF + (wn * 64 + np * 16 + lrow) * ROWB + lcolb);

#pragma unroll
    for (int s = 0; s < 2; s++) {
#pragma unroll
        for (int p = 0; p < 4; p++) {
            cp16(aDst[p] + s * STAGEB, aS[p] + s * BK);
            cp16(bDst[p] + s * STAGEB, bS[p] + s * BK);
        }
        cp_commit();
    }

    const int NKB = K / BK;
    for (int kb = 0; kb < NKB; kb++) {
        cp_wait<1>();
        __syncthreads();

        const int nxt = kb + 2;
        if (nxt < NKB) {
            const uint32_t so = (uint32_t)(nxt % NST) * STAGEB;
#pragma unroll
            for (int p = 0; p < 4; p++) {
                cp16(aDst[p] + so, aS[p] + nxt * BK);
                cp16(bDst[p] + so, bS[p] + nxt * BK);
            }
        }
        cp_commit();

        const uint32_t base = (uint32_t)(kb % NST) * STAGEB;
#pragma unroll
        for (int ks = 0; ks < 2; ks++) {
            const uint32_t ko = base + ks * 32;
            uint32_t af[4][4];
#pragma unroll
            for (int mt = 0; mt < 4; mt++)
                ldsm_x4(af[mt], aAddr[mt] + ko);
            uint32_t bf[8][2];
#pragma unroll
            for (int np = 0; np < 4; np++) {
                uint32_t r[4];
                ldsm_x4(r, bAddr[np] + ko);
                bf[2 * np][0]     = r[0]; bf[2 * np][1]     = r[2];
                bf[2 * np + 1][0] = r[1]; bf[2 * np + 1][1] = r[3];
            }
#pragma unroll
            for (int mt = 0; mt < 4; mt++)
#pragma unroll
                for (int nt = 0; nt < 8; nt++)
                    mma_16816(acc[mt][nt], af[mt], bf[nt]);
        }
    }

    const int cr = lane >> 2;
    const int cc = (lane & 3) * 2;
#pragma unroll
    for (int mt = 0; mt < 4; mt++) {
        const int r0 = m0 + wm * 64 + mt * 16 + cr;
#pragma unroll
        for (int nt = 0; nt < 8; nt++) {
            const int col = n0 + wn * 64 + nt * 8 + cc;
            const float b0 = __ldg(&bias[col]);
            const float b1 = __ldg(&bias[col + 1]);
            float o00 = acc[mt][nt][0] + b0, o01 = acc[mt][nt][1] + b1;
            float o10 = acc[mt][nt][2] + b0, o11 = acc[mt][nt][3] + b1;
            if (QK16 != nullptr) {
                uint32_t w0 = pack2h(__float2half_rn(o00), __float2half_rn(o01));
                uint32_t w1 = pack2h(__float2half_rn(o10), __float2half_rn(o11));
                if (col < 2 * HIDDEN) {
                    *(uint32_t*)&QK16[(size_t)r0 * (2 * HIDDEN) + col] = w0;
                    *(uint32_t*)&QK16[(size_t)(r0 + 8) * (2 * HIDDEN) + col] = w1;
                } else {
                    const int vc = col - 2 * HIDDEN;
                    *(uint32_t*)&V16[(size_t)r0 * HIDDEN + vc] = w0;
                    *(uint32_t*)&V16[(size_t)(r0 + 8) * HIDDEN + vc] = w1;
                }
            } else {
                float2 v0, v1;
                v0.x = o00; v0.y = o01;
                v1.x = o10; v1.y = o11;
                *(float2*)&C[(size_t)r0 * N + col]       = v0;
                *(float2*)&C[(size_t)(r0 + 8) * N + col] = v1;
            }
        }
    }
}

// ---------------------------------------------------------------------------
// All input conversions in one launch (block-range dispatch):
//   [0, A_BLK)           : x fp32 -> fp16 (g_Aq)
//   [A_BLK, +BQ_BLK)     : w_qkv transpose -> g_Bq
//   [A_BLK+BQ_BLK, ...)  : w_proj transpose -> g_Bp
// ---------------------------------------------------------------------------
#define A_BLK  (TOTAL * HIDDEN / 4 / 256)                 /* 10240 */
#define BQ_BLK ((QKVN / 32) * (HIDDEN / 32))              /* 4800  */
#define BP_BLK ((HIDDEN / 32) * (HIDDEN / 32))            /* 1600  */

__global__ __launch_bounds__(256) void convert_all(
    const float* __restrict__ x,
    const float* __restrict__ Wq, const float* __restrict__ Wp)
{
    const int tid = threadIdx.x;

    if (blockIdx.x < A_BLK) {
        int idx = (blockIdx.x * 256 + tid) * 4;
        float4 v = *(const float4*)&x[idx];
        uint32_t p0 = pack2h(__float2half_rn(v.x), __float2half_rn(v.y));
        uint32_t p1 = pack2h(__float2half_rn(v.z), __float2half_rn(v.w));
        *(uint2*)&g_Aq[idx] = make_uint2(p0, p1);
        return;
    }

    // weight transpose path
    const float* W; __half* O; int N, bx, by;
    int b = blockIdx.x - A_BLK;
    if (b < BQ_BLK) {
        W = Wq; O = g_Bq; N = QKVN;
        bx = b % (QKVN / 32); by = b / (QKVN / 32);
    } else {
        b -= BQ_BLK;
        W = Wp; O = g_Bp; N = HIDDEN;
        bx = b % (HIDDEN / 32); by = b / (HIDDEN / 32);
    }
    const int K = HIDDEN;
    const int k0 = by * 32, n0 = bx * 32;
    const int tx = tid & 31, ty = tid >> 5;

    __shared__ float t[32][33];
#pragma unroll
    for (int i = 0; i < 32; i += 8)
        t[ty + i][tx] = W[(size_t)(k0 + ty + i) * N + n0 + tx];
    __syncthreads();
#pragma unroll
    for (int i = 0; i < 32; i += 8) {
        int n = n0 + ty + i, k = k0 + tx;
        O[(size_t)n * K + k] = __float2half_rn(t[tx][ty + i]);
    }
}

// ---------------------------------------------------------------------------
// RoPE (fp16 in/out, vectorized x4; q pre-scaled by hd^-0.5).
// ---------------------------------------------------------------------------
#define RS_BLOCKS (TOTAL * HEADS * 10 / 256)              /* 5120 */

__global__ __launch_bounds__(256) void rope_fp16(
    const float* __restrict__ cosp, const float* __restrict__ sinp)
{
    int idx = blockIdx.x * 256 + threadIdx.x;
    int b = idx % 10;
    int h = (idx / 10) % HEADS;
    int t = idx / (10 * HEADS);
    int d0 = b * 4;

    const __half* row = g_QK16 + (size_t)t * (2 * HIDDEN);
    int qi = h * HEAD_DIM + d0;

    U2H4 q1, q2, k1, k2;
    q1.u = *(const uint2*)&row[qi];
    q2.u = *(const uint2*)&row[qi + 40];
    k1.u = *(const uint2*)&row[HIDDEN + qi];
    k2.u = *(const uint2*)&row[HIDDEN + qi + 40];
    float4 c1 = *(const float4*)&cosp[t * HEAD_DIM + d0];
    float4 s1 = *(const float4*)&sinp[t * HEAD_DIM + d0];
    float4 c2 = *(const float4*)&cosp[t * HEAD_DIM + d0 + 40];
    float4 s2 = *(const float4*)&sinp[t * HEAD_DIM + d0 + 40];

    const float* c1a = &c1.x; const float* s1a = &s1.x;
    const float* c2a = &c2.x; const float* s2a = &s2.x;
    float rq1[4], rq2[4], rk1[4], rk2[4];
#pragma unroll
    for (int i = 0; i < 4; i++) {
        float q1f = __half2float(q1.h[i]), q2f = __half2float(q2.h[i]);
        float k1f = __half2float(k1.h[i]), k2f = __half2float(k2.h[i]);
        rq1[i] = (q1f * c1a[i] - q2f * s1a[i]) * SCALE;
        rq2[i] = (q2f * c2a[i] + q1f * s2a[i]) * SCALE;
        rk1[i] = k1f * c1a[i] - k2f * s1a[i];
        rk2[i] = k2f * c2a[i] + k1f * s2a[i];
    }

    __half* Q = g_Q1 + ((size_t)t * HEADS + h) * HEAD_DIM;
    __half* K = g_K1 + ((size_t)t * HEADS + h) * HEAD_DIM;
    *(uint2*)&Q[d0] = make_uint2(
        pack2h(__float2half_rn(rq1[0]), __float2half_rn(rq1[1])),
        pack2h(__float2half_rn(rq1[2]), __float2half_rn(rq1[3])));
    *(uint2*)&Q[d0 + 40] = make_uint2(
        pack2h(__float2half_rn(rq2[0]), __float2half_rn(rq2[1])),
        pack2h(__float2half_rn(rq2[2]), __float2half_rn(rq2[3])));
    *(uint2*)&K[d0] = make_uint2(
        pack2h(__float2half_rn(rk1[0]), __float2half_rn(rk1[1])),
        pack2h(__float2half_rn(rk1[2]), __float2half_rn(rk1[3])));
    *(uint2*)&K[d0 + 40] = make_uint2(
        pack2h(__float2half_rn(rk2[0]), __float2half_rn(rk2[1])),
        pack2h(__float2half_rn(rk2[2]), __float2half_rn(rk2[3])));
}

// ---------------------------------------------------------------------------
// Tensor-core flash attention. V kept row-major [t][d] in smem, loaded
// directly from g_V16 and fed to the PV MMA via ldmatrix.trans (no vtrans).
// S k = 80, PV k = 64. 63.5KB smem -> 3 CTAs/SM.
// ---------------------------------------------------------------------------
#define LDQ 88    /* 80 + 8 */
#define LDP 72    /* 64 + 8 */
#define LDV 88    /* 80 + 8 (V row-major [t][d]) */
#define SM_Q 0
#define SM_K (SM_Q + 128 * LDQ * 2)       /* 22528 */
#define SM_V (SM_K + 64 * LDQ * 2)        /* 33792 */
#define SM_P (SM_V + 64 * LDV * 2)        /* 45056 */
#define SM_TOT (SM_P + 128 * LDP * 2)     /* 63488 */

__global__ __launch_bounds__(256) void flash_mma()
{
    extern __shared__ char sm[];
    __half (*Q1s)[LDQ] = (__half(*)[LDQ])(sm + SM_Q);
    __half (*K1s)[LDQ] = (__half(*)[LDQ])(sm + SM_K);
    __half (*Vs)[LDV]  = (__half(*)[LDV])(sm + SM_V);
    __half (*P1s)[LDP] = (__half(*)[LDP])(sm + SM_P);

    const int tid  = threadIdx.x;
    const int w    = tid >> 5;
    const int lane = tid & 31;
    const int h    = blockIdx.y;
    const int c    = blockIdx.z;
    const int q0   = c * CHUNK_L + blockIdx.x * 128;

    // load Q tile: 128 x 80 = 1280 uint4
#pragma unroll
    for (int i = 0; i < 5; i++) {
        int idx = tid + i * 256;
        int r = idx / 10, j = idx % 10;
        *(uint4*)&Q1s[r][j * 8] =
            *(const uint4*)&g_Q1[((size_t)(q0 + r) * HEADS + h) * HEAD_DIM + j * 8];
    }

    const int lrow = lane & 15;
    const int lcol = (lane >> 4) << 3;
    const uint32_t qAddr = smem_u32(&Q1s[w * 16 + lrow][lcol]);
    const uint32_t pAddr = smem_u32(&P1s[w * 16 + lrow][lcol]);
    uint32_t kAddr[4], vAddr[5];
#pragma unroll
    for (int np = 0; np < 4; np++)
        kAddr[np] = smem_u32(&K1s[np * 16 + lrow][lcol]);
#pragma unroll
    for (int np = 0; np < 5; np++)
        vAddr[np] = smem_u32(&Vs[lrow][np * 16 + lcol]);   // rows=t, cols=d

    const int cr = lane >> 2;
    const int cc = (lane & 3) * 2;
    uint32_t* Prow0 = (uint32_t*)&P1s[w * 16 + cr][0];
    uint32_t* Prow1 = (uint32_t*)&P1s[w * 16 + cr + 8][0];

    float O[10][4];
#pragma unroll
    for (int nt = 0; nt < 10; nt++)
#pragma unroll
        for (int v = 0; v < 4; v++) O[nt][v] = 0.0f;
    float m0 = -1e30f, m1 = -1e30f, l0 = 0.0f, l1 = 0.0f;

    for (int kt = 0; kt < CHUNK_L / 64; kt++) {
        const int kv0 = kt * 64;
        __syncthreads();
        // load K tile (640 uint4) + V tile row-major (640 uint4)
#pragma unroll
        for (int i = 0; i < 5; i++) {
            int idx = tid + i * 256;
            int r = (idx % 640) / 10, j = idx % 10;
            if (idx < 640) {
                *(uint4*)&K1s[r][j * 8] =
                    *(const uint4*)&g_K1[((size_t)(c * CHUNK_L + kv0 + r) * HEADS + h) * HEAD_DIM + j * 8];
            } else {
                *(uint4*)&Vs[r][j * 8] =
                    *(const uint4*)&g_V16[(size_t)(c * CHUNK_L + kv0 + r) * HIDDEN + h * HEAD_DIM + j * 8];
            }
        }
        __syncthreads();

        // ---- S = Q @ K^T (k = 80) ----
        float s[8][4];
#pragma unroll
        for (int nt = 0; nt < 8; nt++)
#pragma unroll
            for (int v = 0; v < 4; v++) s[nt][v] = 0.0f;
#pragma unroll
        for (int ks = 0; ks < 5; ks++) {
            uint32_t af[4];
            ldsm_x4(af, qAddr + ks * 32);
            uint32_t bf[8][2];
#pragma unroll
            for (int np = 0; np < 4; np++) {
                uint32_t r[4];
                ldsm_x4(r, kAddr[np] + ks * 32);
                bf[2 * np][0]     = r[0]; bf[2 * np][1]     = r[2];
                bf[2 * np + 1][0] = r[1]; bf[2 * np + 1][1] = r[3];
            }
#pragma unroll
            for (int nt = 0; nt < 8; nt++)
                mma_16816(s[nt], af, bf[nt]);
        }

        // ---- online softmax ----
        float tm0 = -1e30f, tm1 = -1e30f;
#pragma unroll
        for (int nt = 0; nt < 8; nt++) {
            tm0 = fmaxf(tm0, fmaxf(s[nt][0], s[nt][1]));
            tm1 = fmaxf(tm1, fmaxf(s[nt][2], s[nt][3]));
        }
        tm0 = fmaxf(tm0, __shfl_xor_sync(0xffffffffu, tm0, 1));
        tm0 = fmaxf(tm0, __shfl_xor_sync(0xffffffffu, tm0, 2));
        tm1 = fmaxf(tm1, __shfl_xor_sync(0xffffffffu, tm1, 1));
        tm1 = fmaxf(tm1, __shfl_xor_sync(0xffffffffu, tm1, 2));
        const float nm0 = fmaxf(m0, tm0);
        const float nm1 = fmaxf(m1, tm1);
        const float a0 = __expf(m0 - nm0);
        const float a1 = __expf(m1 - nm1);
        m0 = nm0; m1 = nm1;

        float sum0 = 0.0f, sum1 = 0.0f;
#pragma unroll
        for (int nt = 0; nt < 8; nt++) {
            float p00 = __expf(s[nt][0] - nm0);
            float p01 = __expf(s[nt][1] - nm0);
            float p10 = __expf(s[nt][2] - nm1);
            float p11 = __expf(s[nt][3] - nm1);
            sum0 += p00 + p01;
            sum1 += p10 + p11;
            const int cw = (nt * 8 + cc) >> 1;
            Prow0[cw] = pack2h(__float2half_rn(p00), __float2half_rn(p01));
            Prow1[cw] = pack2h(__float2half_rn(p10), __float2half_rn(p11));
        }
        sum0 += __shfl_xor_sync(0xffffffffu, sum0, 1);
        sum0 += __shfl_xor_sync(0xffffffffu, sum0, 2);
        sum1 += __shfl_xor_sync(0xffffffffu, sum1, 1);
        sum1 += __shfl_xor_sync(0xffffffffu, sum1, 2);
        l0 = l0 * a0 + sum0;
        l1 = l1 * a1 + sum1;

#pragma unroll
        for (int nt = 0; nt < 10; nt++) {
            O[nt][0] *= a0; O[nt][1] *= a0;
            O[nt][2] *= a1; O[nt][3] *= a1;
        }
        __syncthreads();

        // ---- O += P @ V (k = 64, n = 80) — V row-major via ldmatrix.trans ----
#pragma unroll
        for (int ks = 0; ks < 4; ks++) {
            uint32_t af[4];
            ldsm_x4(af, pAddr + ks * 32);
            uint32_t bf[10][2];
#pragma unroll
            for (int np = 0; np < 5; np++) {
                uint32_t r[4];
                ldsm_x4_t(r, vAddr[np] + ks * (16 * LDV * 2));
                // trans pairing: bf[2np]={r0,r1} (d0-7), bf[2np+1]={r2,r3} (d8-15)
                bf[2 * np][0]     = r[0]; bf[2 * np][1]     = r[1];
                bf[2 * np + 1][0] = r[2]; bf[2 * np + 1][1] = r[3];
            }
#pragma unroll
            for (int nt = 0; nt < 10; nt++)
                mma_16816(O[nt], af, bf[nt]);
        }
    }

    // ---- normalize + single-fp16 output into g_Ap ----
    const float inv0 = 1.0f / l0;
    const float inv1 = 1.0f / l1;
    const int r0 = q0 + w * 16 + cr;
#pragma unroll
    for (int nt = 0; nt < 10; nt++) {
        const int col = h * HEAD_DIM + nt * 8 + cc;
        *(uint32_t*)&g_Ap[(size_t)r0 * HIDDEN + col] =
            pack2h(__float2half_rn(O[nt][0] * inv0),
                   __float2half_rn(O[nt][1] * inv0));
        *(uint32_t*)&g_Ap[(size_t)(r0 + 8) * HIDDEN + col] =
            pack2h(__float2half_rn(O[nt][2] * inv1),
                   __float2half_rn(O[nt][3] * inv1));
    }
}

// ---------------------------------------------------------------------------
extern "C" void kernel_launch(void* const* d_in, const int* in_sizes, int n_in,
                              void* d_out, int out_size)
{
    (void)in_sizes; (void)n_in; (void)out_size;
    const float* x      = (const float*)d_in[0];
    const float* cosp   = (const float*)d_in[1];
    const float* sinp   = (const float*)d_in[2];
    const float* w_qkv  = (const float*)d_in[3];
    const float* b_qkv  = (const float*)d_in[4];
    const float* w_proj = (const float*)d_in[5];
    const float* b_proj = (const float*)d_in[6];
    float* out = (float*)d_out;

    __half *Aq = nullptr, *Ap = nullptr, *Bq = nullptr, *Bp = nullptr;
    __half *QK16 = nullptr, *V16 = nullptr;
    cudaGetSymbolAddress((void**)&Aq,   g_Aq);
    cudaGetSymbolAddress((void**)&Ap,   g_Ap);
    cudaGetSymbolAddress((void**)&Bq,   g_Bq);
    cudaGetSymbolAddress((void**)&Bp,   g_Bp);
    cudaGetSymbolAddress((void**)&QK16, g_QK16);
    cudaGetSymbolAddress((void**)&V16,  g_V16);

    cudaFuncSetAttribute(gemm_fp16_mma,
                         cudaFuncAttributeMaxDynamicSharedMemorySize, GSMEM);
    cudaFuncSetAttribute(flash_mma,
                         cudaFuncAttributeMaxDynamicSharedMemorySize, SM_TOT);

    // all input conversions in one launch
    convert_all<<<A_BLK + BQ_BLK + BP_BLK, 256>>>(x, w_qkv, w_proj);

    // 1) QKV projection -> q,k fp16 (g_QK16), v fp16 (g_V16)
    gemm_fp16_mma<<<dim3(QKVN / 128, TOTAL / 128), 128, GSMEM>>>(
        Aq, Bq, b_qkv, nullptr, QK16, V16, QKVN, HIDDEN);

    // 2) RoPE
    rope_fp16<<<RS_BLOCKS, 256>>>(cosp, sinp);

    // 3) flash attention (V direct from g_V16, ldmatrix.trans)
    flash_mma<<<dim3(CHUNK_L / 128, HEADS, NCHUNK), 256, SM_TOT>>>();

    // 4) output projection (fp32 out)
    gemm_fp16_mma<<<dim3(HIDDEN / 128, TOTAL / 128), 128, GSMEM>>>(
        Ap, Bp, b_proj, out, nullptr, nullptr, HIDDEN, HIDDEN);
}

// round 15
// speedup vs baseline: 1.0989x; 1.0989x over previous
#include <cuda_runtime.h>
#include <cuda_fp16.h>
#include <cstdint>

#define TOTAL    8192
#define HIDDEN   1280
#define HEADS    16
#define HEAD_DIM 80
#define NCHUNK   8
#define CHUNK_L  1024
#define QKVN     3840
#define SCALE    0.11180339887498949f  /* 80^-0.5 */

// ---------------- device scratch (no allocs allowed) ----------------
__device__ __half g_QK16[(size_t)TOTAL * 2 * HIDDEN];      // fp16 q|k (GEMM epi)
__device__ __half g_V16 [(size_t)TOTAL * HIDDEN];          // fp16 v  (GEMM epi)
__device__ __half g_Aq  [(size_t)TOTAL * HIDDEN];          // fp16(x)
__device__ __half g_Ap  [(size_t)TOTAL * HIDDEN];          // fp16(attn)
__device__ __half g_Bq  [(size_t)QKVN  * HIDDEN];          // fp16(w_qkv)^T
__device__ __half g_Bp  [(size_t)HIDDEN* HIDDEN];          // fp16(w_proj)^T
__device__ __half g_Q1 [(size_t)TOTAL * HEADS * HEAD_DIM]; // fp16 roped q
__device__ __half g_K1 [(size_t)TOTAL * HEADS * HEAD_DIM]; // fp16 roped k
__device__ __half g_Vt [(size_t)NCHUNK * HEADS * HEAD_DIM * CHUNK_L];

// ---------------- PTX helpers ----------------
__device__ __forceinline__ uint32_t smem_u32(const void* p) {
    uint32_t a;
    asm("{ .reg .u64 t; cvta.to.shared.u64 t, %1; cvt.u32.u64 %0, t; }"
        : "=r"(a) : "l"(p));
    return a;
}
__device__ __forceinline__ void ldsm_x4(uint32_t* r, uint32_t addr) {
    asm volatile("ldmatrix.sync.aligned.m8n8.x4.shared.b16 {%0,%1,%2,%3}, [%4];"
                 : "=r"(r[0]), "=r"(r[1]), "=r"(r[2]), "=r"(r[3]) : "r"(addr));
}
__device__ __forceinline__ void mma_16816(float* c, const uint32_t* a,
                                          const uint32_t* b) {
    asm volatile(
        "mma.sync.aligned.m16n8k16.row.col.f32.f16.f16.f32 "
        "{%0,%1,%2,%3}, {%4,%5,%6,%7}, {%8,%9}, {%0,%1,%2,%3};"
        : "+f"(c[0]), "+f"(c[1]), "+f"(c[2]), "+f"(c[3])
        : "r"(a[0]), "r"(a[1]), "r"(a[2]), "r"(a[3]), "r"(b[0]), "r"(b[1]));
}
__device__ __forceinline__ void cp16(uint32_t dst, const void* src) {
    asm volatile("cp.async.cg.shared.global [%0], [%1], 16;"
                 :: "r"(dst), "l"(src));
}
__device__ __forceinline__ void cp_commit() {
    asm volatile("cp.async.commit_group;" ::: "memory");
}
template <int W>
__device__ __forceinline__ void cp_wait() {
    asm volatile("cp.async.wait_group %0;" :: "n"(W) : "memory");
}
__device__ __forceinline__ uint32_t pack2h(__half lo, __half hi) {
    return (uint32_t)__half_as_ushort(lo) |
           ((uint32_t)__half_as_ushort(hi) << 16);
}
union U2H4 { uint2 u; __half h[4]; };

// ---------------------------------------------------------------------------
// Tensor-core GEMM: out = A * B^T + bias. QKV mode (QK16 != null): fp16 out,
// cols < 2*HIDDEN to QK16, rest to V16. Proj mode: fp32 to C.
// ---------------------------------------------------------------------------
#define BK     32
#define NST    3
#define LDAE   40
#define ROWB   (LDAE * 2)
#define STAGEB (128 * ROWB)
#define BOFF   (NST * STAGEB)
#define GSMEM  (2 * NST * STAGEB)

__global__ __launch_bounds__(128, 2) void gemm_fp16_mma(
    const __half* __restrict__ A, const __half* __restrict__ B,
    const float* __restrict__ bias, float* __restrict__ C,
    __half* __restrict__ QK16, __half* __restrict__ V16, int N, int K)
{
    extern __shared__ char sm[];
    const int tid  = threadIdx.x;
    const int wid  = tid >> 5;
    const int lane = tid & 31;
    const int m0   = blockIdx.y * 128;
    const int n0   = blockIdx.x * 128;
    const int wm   = wid & 1;
    const int wn   = wid >> 1;

    uint32_t aDst[4], bDst[4];
    const __half *aS[4], *bS[4];
#pragma unroll
    for (int p = 0; p < 4; p++) {
        int u  = tid + p * 128;
        int r  = u >> 2;
        int ch = (u & 3) * 8;
        aDst[p] = smem_u32(sm + r * ROWB + ch * 2);
        bDst[p] = aDst[p] + BOFF;
        aS[p]   = A + (size_t)(m0 + r) * K + ch;
        bS[p]   = B + (size_t)(n0 + r) * K + ch;
    }

    float acc[4][8][4];
#pragma unroll
    for (int mt = 0; mt < 4; mt++)
#pragma unroll
        for (int nt = 0; nt < 8; nt++)
#pragma unroll
            for (int v = 0; v < 4; v++) acc[mt][nt][v] = 0.0f;

    const int lrow  = lane & 15;
    const int lcolb = ((lane >> 4) << 3) * 2;
    uint32_t aAddr[4], bAddr[4];
#pragma unroll
    for (int mt = 0; mt < 4; mt++)
        aAddr[mt] = smem_u32(sm + (wm * 64 + mt * 16 + lrow) * ROWB + lcolb);
#pragma unroll
    for (int np = 0; np < 4; np++)
        bAddr[np] = smem_u32(sm + BOFF + (wn * 64 + np * 16 + lrow) * ROWB + lcolb);

#pragma unroll
    for (int s = 0; s < 2; s++) {
#pragma unroll
        for (int p = 0; p < 4; p++) {
            cp16(aDst[p] + s * STAGEB, aS[p] + s * BK);
            cp16(bDst[p] + s * STAGEB, bS[p] + s * BK);
        }
        cp_commit();
    }

    const int NKB = K / BK;
    for (int kb = 0; kb < NKB; kb++) {
        cp_wait<1>();
        __syncthreads();

        const int nxt = kb + 2;
        if (nxt < NKB) {
            const uint32_t so = (uint32_t)(nxt % NST) * STAGEB;
#pragma unroll
            for (int p = 0; p < 4; p++) {
                cp16(aDst[p] + so, aS[p] + nxt * BK);
                cp16(bDst[p] + so, bS[p] + nxt * BK);
            }
        }
        cp_commit();

        const uint32_t base = (uint32_t)(kb % NST) * STAGEB;
#pragma unroll
        for (int ks = 0; ks < 2; ks++) {
            const uint32_t ko = base + ks * 32;
            uint32_t af[4][4];
#pragma unroll
            for (int mt = 0; mt < 4; mt++)
                ldsm_x4(af[mt], aAddr[mt] + ko);
            uint32_t bf[8][2];
#pragma unroll
            for (int np = 0; np < 4; np++) {
                uint32_t r[4];
                ldsm_x4(r, bAddr[np] + ko);
                bf[2 * np][0]     = r[0]; bf[2 * np][1]     = r[2];
                bf[2 * np + 1][0] = r[1]; bf[2 * np + 1][1] = r[3];
            }
#pragma unroll
            for (int mt = 0; mt < 4; mt++)
#pragma unroll
                for (int nt = 0; nt < 8; nt++)
                    mma_16816(acc[mt][nt], af[mt], bf[nt]);
        }
    }

    const int cr = lane >> 2;
    const int cc = (lane & 3) * 2;
#pragma unroll
    for (int mt = 0; mt < 4; mt++) {
        const int r0 = m0 + wm * 64 + mt * 16 + cr;
#pragma unroll
        for (int nt = 0; nt < 8; nt++) {
            const int col = n0 + wn * 64 + nt * 8 + cc;
            const float b0 = __ldg(&bias[col]);
            const float b1 = __ldg(&bias[col + 1]);
            float o00 = acc[mt][nt][0] + b0, o01 = acc[mt][nt][1] + b1;
            float o10 = acc[mt][nt][2] + b0, o11 = acc[mt][nt][3] + b1;
            if (QK16 != nullptr) {
                uint32_t w0 = pack2h(__float2half_rn(o00), __float2half_rn(o01));
                uint32_t w1 = pack2h(__float2half_rn(o10), __float2half_rn(o11));
                if (col < 2 * HIDDEN) {
                    *(uint32_t*)&QK16[(size_t)r0 * (2 * HIDDEN) + col] = w0;
                    *(uint32_t*)&QK16[(size_t)(r0 + 8) * (2 * HIDDEN) + col] = w1;
                } else {
                    const int vc = col - 2 * HIDDEN;
                    *(uint32_t*)&V16[(size_t)r0 * HIDDEN + vc] = w0;
                    *(uint32_t*)&V16[(size_t)(r0 + 8) * HIDDEN + vc] = w1;
                }
            } else {
                float2 v0, v1;
                v0.x = o00; v0.y = o01;
                v1.x = o10; v1.y = o11;
                *(float2*)&C[(size_t)r0 * N + col]       = v0;
                *(float2*)&C[(size_t)(r0 + 8) * N + col] = v1;
            }
        }
    }
}

// ---------------------------------------------------------------------------
// All input conversions in one launch (block-range dispatch):
//   [0, A_BLK)           : x fp32 -> fp16 (g_Aq)
//   [A_BLK, +BQ_BLK)     : w_qkv transpose -> g_Bq
//   [A_BLK+BQ_BLK, ...)  : w_proj transpose -> g_Bp
// ---------------------------------------------------------------------------
#define A_BLK  (TOTAL * HIDDEN / 4 / 256)                 /* 10240 */
#define BQ_BLK ((QKVN / 32) * (HIDDEN / 32))              /* 4800  */
#define BP_BLK ((HIDDEN / 32) * (HIDDEN / 32))            /* 1600  */

__global__ __launch_bounds__(256) void convert_all(
    const float* __restrict__ x,
    const float* __restrict__ Wq, const float* __restrict__ Wp)
{
    const int tid = threadIdx.x;

    if (blockIdx.x < A_BLK) {
        int idx = (blockIdx.x * 256 + tid) * 4;
        float4 v = *(const float4*)&x[idx];
        uint32_t p0 = pack2h(__float2half_rn(v.x), __float2half_rn(v.y));
        uint32_t p1 = pack2h(__float2half_rn(v.z), __float2half_rn(v.w));
        *(uint2*)&g_Aq[idx] = make_uint2(p0, p1);
        return;
    }

    const float* W; __half* O; int N, bx, by;
    int b = blockIdx.x - A_BLK;
    if (b < BQ_BLK) {
        W = Wq; O = g_Bq; N = QKVN;
        bx = b % (QKVN / 32); by = b / (QKVN / 32);
    } else {
        b -= BQ_BLK;
        W = Wp; O = g_Bp; N = HIDDEN;
        bx = b % (HIDDEN / 32); by = b / (HIDDEN / 32);
    }
    const int K = HIDDEN;
    const int k0 = by * 32, n0 = bx * 32;
    const int tx = tid & 31, ty = tid >> 5;

    __shared__ float t[32][33];
#pragma unroll
    for (int i = 0; i < 32; i += 8)
        t[ty + i][tx] = W[(size_t)(k0 + ty + i) * N + n0 + tx];
    __syncthreads();
#pragma unroll
    for (int i = 0; i < 32; i += 8) {
        int n = n0 + ty + i, k = k0 + tx;
        O[(size_t)n * K + k] = __float2half_rn(t[tx][ty + i]);
    }
}

// ---------------------------------------------------------------------------
// Fused RoPE (fp16 in/out, vectorized x4) + V transpose, one launch (R13).
// ---------------------------------------------------------------------------
#define RS_BLOCKS (TOTAL * HEADS * 10 / 256)         /* 5120 */
#define VT_BLOCKS ((TOTAL / 64) * HEADS)             /* 2048 */

__global__ __launch_bounds__(256) void rope_vtrans(
    const float* __restrict__ cosp, const float* __restrict__ sinp)
{
    __shared__ __half vs[64][88];
    const int tid = threadIdx.x;

    if (blockIdx.x < RS_BLOCKS) {
        int idx = blockIdx.x * 256 + tid;
        int b = idx % 10;
        int h = (idx / 10) % HEADS;
        int t = idx / (10 * HEADS);
        int d0 = b * 4;

        const __half* row = g_QK16 + (size_t)t * (2 * HIDDEN);
        int qi = h * HEAD_DIM + d0;

        U2H4 q1, q2, k1, k2;
        q1.u = *(const uint2*)&row[qi];
        q2.u = *(const uint2*)&row[qi + 40];
        k1.u = *(const uint2*)&row[HIDDEN + qi];
        k2.u = *(const uint2*)&row[HIDDEN + qi + 40];
        float4 c1 = *(const float4*)&cosp[t * HEAD_DIM + d0];
        float4 s1 = *(const float4*)&sinp[t * HEAD_DIM + d0];
        float4 c2 = *(const float4*)&cosp[t * HEAD_DIM + d0 + 40];
        float4 s2 = *(const float4*)&sinp[t * HEAD_DIM + d0 + 40];

        const float* c1a = &c1.x; const float* s1a = &s1.x;
        const float* c2a = &c2.x; const float* s2a = &s2.x;
        float rq1[4], rq2[4], rk1[4], rk2[4];
#pragma unroll
        for (int i = 0; i < 4; i++) {
            float q1f = __half2float(q1.h[i]), q2f = __half2float(q2.h[i]);
            float k1f = __half2float(k1.h[i]), k2f = __half2float(k2.h[i]);
            rq1[i] = (q1f * c1a[i] - q2f * s1a[i]) * SCALE;
            rq2[i] = (q2f * c2a[i] + q1f * s2a[i]) * SCALE;
            rk1[i] = k1f * c1a[i] - k2f * s1a[i];
            rk2[i] = k2f * c2a[i] + k1f * s2a[i];
        }

        __half* Q = g_Q1 + ((size_t)t * HEADS + h) * HEAD_DIM;
        __half* K = g_K1 + ((size_t)t * HEADS + h) * HEAD_DIM;
        *(uint2*)&Q[d0] = make_uint2(
            pack2h(__float2half_rn(rq1[0]), __float2half_rn(rq1[1])),
            pack2h(__float2half_rn(rq1[2]), __float2half_rn(rq1[3])));
        *(uint2*)&Q[d0 + 40] = make_uint2(
            pack2h(__float2half_rn(rq2[0]), __float2half_rn(rq2[1])),
            pack2h(__float2half_rn(rq2[2]), __float2half_rn(rq2[3])));
        *(uint2*)&K[d0] = make_uint2(
            pack2h(__float2half_rn(rk1[0]), __float2half_rn(rk1[1])),
            pack2h(__float2half_rn(rk1[2]), __float2half_rn(rk1[3])));
        *(uint2*)&K[d0 + 40] = make_uint2(
            pack2h(__float2half_rn(rk2[0]), __float2half_rn(rk2[1])),
            pack2h(__float2half_rn(rk2[2]), __float2half_rn(rk2[3])));
    } else {
        const int vb = blockIdx.x - RS_BLOCKS;
        const int t0 = (vb % (TOTAL / 64)) * 64;
        const int h  = vb / (TOTAL / 64);
        const int c  = t0 / CHUNK_L;
        const int tloc = t0 - c * CHUNK_L;

#pragma unroll
        for (int i = 0; i < 3; i++) {
            int idx = tid + i * 256;
            if (idx < 640) {
                int r = idx / 10, j = idx % 10;
                *(uint4*)&vs[r][j * 8] =
                    *(const uint4*)&g_V16[(size_t)(t0 + r) * HIDDEN + h * HEAD_DIM + j * 8];
            }
        }
        __syncthreads();

#pragma unroll
        for (int i = 0; i < 5; i++) {
            int idx = tid + i * 256;
            int d = idx / 16, t4 = (idx % 16) * 4;
            uint2 w;
            w.x = pack2h(vs[t4 + 0][d], vs[t4 + 1][d]);
            w.y = pack2h(vs[t4 + 2][d], vs[t4 + 3][d]);
            *(uint2*)&g_Vt[((size_t)(c * HEADS + h) * HEAD_DIM + d) * CHUNK_L
                           + tloc + t4] = w;
        }
    }
}

// ---------------------------------------------------------------------------
// Tensor-core flash attention — verified R10/R12/R13 version
// (single-buffer, 63.7KB smem, 3 CTA/SM, non-trans ldmatrix only).
// ---------------------------------------------------------------------------
#define LDQ 88    /* 80 + 8 */
#define LDP 72    /* 64 + 8 */
#define SM_Q 0
#define SM_K (SM_Q + 128 * LDQ * 2)       /* 22528 */
#define SM_V (SM_K + 64 * LDQ * 2)        /* 33792 */
#define SM_P (SM_V + 80 * LDP * 2)        /* 45312 */
#define SM_TOT (SM_P + 128 * LDP * 2)     /* 63744 */

__global__ __launch_bounds__(256) void flash_mma()
{
    extern __shared__ char sm[];
    __half (*Q1s)[LDQ] = (__half(*)[LDQ])(sm + SM_Q);
    __half (*K1s)[LDQ] = (__half(*)[LDQ])(sm + SM_K);
    __half (*Vts)[LDP] = (__half(*)[LDP])(sm + SM_V);
    __half (*P1s)[LDP] = (__half(*)[LDP])(sm + SM_P);

    const int tid  = threadIdx.x;
    const int w    = tid >> 5;
    const int lane = tid & 31;
    const int h    = blockIdx.y;
    const int c    = blockIdx.z;
    const int q0   = c * CHUNK_L + blockIdx.x * 128;

#pragma unroll
    for (int i = 0; i < 5; i++) {
        int idx = tid + i * 256;
        int r = idx / 10, j = idx % 10;
        *(uint4*)&Q1s[r][j * 8] =
            *(const uint4*)&g_Q1[((size_t)(q0 + r) * HEADS + h) * HEAD_DIM + j * 8];
    }

    const int lrow = lane & 15;
    const int lcol = (lane >> 4) << 3;
    const uint32_t qAddr = smem_u32(&Q1s[w * 16 + lrow][lcol]);
    const uint32_t pAddr = smem_u32(&P1s[w * 16 + lrow][lcol]);
    uint32_t kAddr[4], vAddr[5];
#pragma unroll
    for (int np = 0; np < 4; np++)
        kAddr[np] = smem_u32(&K1s[np * 16 + lrow][lcol]);
#pragma unroll
    for (int np = 0; np < 5; np++)
        vAddr[np] = smem_u32(&Vts[np * 16 + lrow][lcol]);

    const int cr = lane >> 2;
    const int cc = (lane & 3) * 2;
    uint32_t* Prow0 = (uint32_t*)&P1s[w * 16 + cr][0];
    uint32_t* Prow1 = (uint32_t*)&P1s[w * 16 + cr + 8][0];

    float O[10][4];
#pragma unroll
    for (int nt = 0; nt < 10; nt++)
#pragma unroll
        for (int v = 0; v < 4; v++) O[nt][v] = 0.0f;
    float m0 = -1e30f, m1 = -1e30f, l0 = 0.0f, l1 = 0.0f;

    const size_t vBase = (size_t)(c * HEADS + h) * HEAD_DIM * CHUNK_L;

    for (int kt = 0; kt < CHUNK_L / 64; kt++) {
        const int kv0 = kt * 64;
        __syncthreads();
#pragma unroll
        for (int i = 0; i < 5; i++) {
            int idx = tid + i * 256;
            if (idx < 640) {
                int r = idx / 10, j = idx % 10;
                *(uint4*)&K1s[r][j * 8] =
                    *(const uint4*)&g_K1[((size_t)(c * CHUNK_L + kv0 + r) * HEADS + h) * HEAD_DIM + j * 8];
            } else {
                int vx = idx - 640;
                int d = vx >> 3, j = vx & 7;
                *(uint4*)&Vts[d][j * 8] =
                    *(const uint4*)&g_Vt[vBase + (size_t)d * CHUNK_L + kv0 + j * 8];
            }
        }
        __syncthreads();

        float s[8][4];
#pragma unroll
        for (int nt = 0; nt < 8; nt++)
#pragma unroll
            for (int v = 0; v < 4; v++) s[nt][v] = 0.0f;
#pragma unroll
        for (int ks = 0; ks < 5; ks++) {
            uint32_t af[4];
            ldsm_x4(af, qAddr + ks * 32);
            uint32_t bf[8][2];
#pragma unroll
            for (int np = 0; np < 4; np++) {
                uint32_t r[4];
                ldsm_x4(r, kAddr[np] + ks * 32);
                bf[2 * np][0]     = r[0]; bf[2 * np][1]     = r[2];
                bf[2 * np + 1][0] = r[1]; bf[2 * np + 1][1] = r[3];
            }
#pragma unroll
            for (int nt = 0; nt < 8; nt++)
                mma_16816(s[nt], af, bf[nt]);
        }

        float tm0 = -1e30f, tm1 = -1e30f;
#pragma unroll
        for (int nt = 0; nt < 8; nt++) {
            tm0 = fmaxf(tm0, fmaxf(s[nt][0], s[nt][1]));
            tm1 = fmaxf(tm1, fmaxf(s[nt][2], s[nt][3]));
        }
        tm0 = fmaxf(tm0, __shfl_xor_sync(0xffffffffu, tm0, 1));
        tm0 = fmaxf(tm0, __shfl_xor_sync(0xffffffffu, tm0, 2));
        tm1 = fmaxf(tm1, __shfl_xor_sync(0xffffffffu, tm1, 1));
        tm1 = fmaxf(tm1, __shfl_xor_sync(0xffffffffu, tm1, 2));
        const float nm0 = fmaxf(m0, tm0);
        const float nm1 = fmaxf(m1, tm1);
        const float a0 = __expf(m0 - nm0);
        const float a1 = __expf(m1 - nm1);
        m0 = nm0; m1 = nm1;

        float sum0 = 0.0f, sum1 = 0.0f;
#pragma unroll
        for (int nt = 0; nt < 8; nt++) {
            float p00 = __expf(s[nt][0] - nm0);
            float p01 = __expf(s[nt][1] - nm0);
            float p10 = __expf(s[nt][2] - nm1);
            float p11 = __expf(s[nt][3] - nm1);
            sum0 += p00 + p01;
            sum1 += p10 + p11;
            const int cw = (nt * 8 + cc) >> 1;
            Prow0[cw] = pack2h(__float2half_rn(p00), __float2half_rn(p01));
            Prow1[cw] = pack2h(__float2half_rn(p10), __float2half_rn(p11));
        }
        sum0 += __shfl_xor_sync(0xffffffffu, sum0, 1);
        sum0 += __shfl_xor_sync(0xffffffffu, sum0, 2);
        sum1 += __shfl_xor_sync(0xffffffffu, sum1, 1);
        sum1 += __shfl_xor_sync(0xffffffffu, sum1, 2);
        l0 = l0 * a0 + sum0;
        l1 = l1 * a1 + sum1;

#pragma unroll
        for (int nt = 0; nt < 10; nt++) {
            O[nt][0] *= a0; O[nt][1] *= a0;
            O[nt][2] *= a1; O[nt][3] *= a1;
        }
        __syncthreads();

#pragma unroll
        for (int ks = 0; ks < 4; ks++) {
            uint32_t af[4];
            ldsm_x4(af, pAddr + ks * 32);
            uint32_t bf[10][2];
#pragma unroll
            for (int np = 0; np < 5; np++) {
                uint32_t r[4];
                ldsm_x4(r, vAddr[np] + ks * 32);
                bf[2 * np][0]     = r[0]; bf[2 * np][1]     = r[2];
                bf[2 * np + 1][0] = r[1]; bf[2 * np + 1][1] = r[3];
            }
#pragma unroll
            for (int nt = 0; nt < 10; nt++)
                mma_16816(O[nt], af, bf[nt]);
        }
    }

    const float inv0 = 1.0f / l0;
    const float inv1 = 1.0f / l1;
    const int r0 = q0 + w * 16 + cr;
#pragma unroll
    for (int nt = 0; nt < 10; nt++) {
        const int col = h * HEAD_DIM + nt * 8 + cc;
        *(uint32_t*)&g_Ap[(size_t)r0 * HIDDEN + col] =
            pack2h(__float2half_rn(O[nt][0] * inv0),
                   __float2half_rn(O[nt][1] * inv0));
        *(uint32_t*)&g_Ap[(size_t)(r0 + 8) * HIDDEN + col] =
            pack2h(__float2half_rn(O[nt][2] * inv1),
                   __float2half_rn(O[nt][3] * inv1));
    }
}

// ---------------------------------------------------------------------------
extern "C" void kernel_launch(void* const* d_in, const int* in_sizes, int n_in,
                              void* d_out, int out_size)
{
    (void)in_sizes; (void)n_in; (void)out_size;
    const float* x      = (const float*)d_in[0];
    const float* cosp   = (const float*)d_in[1];
    const float* sinp   = (const float*)d_in[2];
    const float* w_qkv  = (const float*)d_in[3];
    const float* b_qkv  = (const float*)d_in[4];
    const float* w_proj = (const float*)d_in[5];
    const float* b_proj = (const float*)d_in[6];
    float* out = (float*)d_out;

    __half *Aq = nullptr, *Ap = nullptr, *Bq = nullptr, *Bp = nullptr;
    __half *QK16 = nullptr, *V16 = nullptr;
    cudaGetSymbolAddress((void**)&Aq,   g_Aq);
    cudaGetSymbolAddress((void**)&Ap,   g_Ap);
    cudaGetSymbolAddress((void**)&Bq,   g_Bq);
    cudaGetSymbolAddress((void**)&Bp,   g_Bp);
    cudaGetSymbolAddress((void**)&QK16, g_QK16);
    cudaGetSymbolAddress((void**)&V16,  g_V16);

    cudaFuncSetAttribute(gemm_fp16_mma,
                         cudaFuncAttributeMaxDynamicSharedMemorySize, GSMEM);
    cudaFuncSetAttribute(flash_mma,
                         cudaFuncAttributeMaxDynamicSharedMemorySize, SM_TOT);

    // all input conversions in one launch
    convert_all<<<A_BLK + BQ_BLK + BP_BLK, 256>>>(x, w_qkv, w_proj);

    // 1) QKV projection -> q,k fp16 (g_QK16), v fp16 (g_V16)
    gemm_fp16_mma<<<dim3(QKVN / 128, TOTAL / 128), 128, GSMEM>>>(
        Aq, Bq, b_qkv, nullptr, QK16, V16, QKVN, HIDDEN);

    // 2) fused RoPE + V transpose
    rope_vtrans<<<RS_BLOCKS + VT_BLOCKS, 256>>>(cosp, sinp);

    // 3) flash attention (writes fp16 attn into g_Ap)
    flash_mma<<<dim3(CHUNK_L / 128, HEADS, NCHUNK), 256, SM_TOT>>>();

    // 4) output projection (fp32 out)
    gemm_fp16_mma<<<dim3(HIDDEN / 128, TOTAL / 128), 128, GSMEM>>>(
        Ap, Bp, b_proj, out, nullptr, nullptr, HIDDEN, HIDDEN);
}